// round 3
// baseline (speedup 1.0000x reference)
#include <cuda_runtime.h>

#define BB 8
#define NN 256
#define DD 3
#define FF 32
#define NRBF 50
#define HH 128
#define EPSV 1e-6f
#define NP (NN-1)             // 255 neighbors
#define ROWLEN (NN*DD + NN*FF) // 8960

// scratch (alloc-free rule: __device__ globals)
__device__ float g_vx[BB*NN*3];
__device__ float g_tp[BB*NN];

// shared layout (floats)
#define OFF_S1W   0
#define OFF_S2W   (OFF_S1W + NRBF*HH)        // 6400
#define OFF_FW    (OFF_S2W + NRBF*HH)        // 12800
#define OFF_XALL  (OFF_FW  + NRBF*HH)        // 19200
#define OFF_FEATS (OFF_XALL + NN*3)          // 19968
#define OFF_SMF   (OFF_FEATS + FF)           // 20000
#define OFF_MUS   (OFF_SMF + FF)             // 20032
#define OFF_C1    (OFF_MUS + 64)             // 20096 (mus padded to 64)
#define OFF_C2    (OFF_C1 + HH)
#define OFF_CF    (OFF_C2 + HH)
#define OFF_W2A   (OFF_CF + HH)
#define OFF_W2B   (OFF_W2A + HH)
#define OFF_HFT   (OFF_W2B + HH)
#define OFF_BACC  (OFF_HFT + HH)
#define SMEM_FLOATS (OFF_BACC + 8)
#define SMEM_BYTES (SMEM_FLOATS * 4)

__global__ __launch_bounds__(256, 2)
void fd_site_kernel(const float* __restrict__ state,
                    const float* __restrict__ mus,
                    const float* __restrict__ gamma_p,
                    const float* __restrict__ s1_W1, const float* __restrict__ s1_b1,
                    const float* __restrict__ s1_W2, const float* __restrict__ s1_b2,
                    const float* __restrict__ s2_W1, const float* __restrict__ s2_b1,
                    const float* __restrict__ s2_W2, const float* __restrict__ s2_b2,
                    const float* __restrict__ f_W1,  const float* __restrict__ f_b1,
                    const float* __restrict__ f_W2,  const float* __restrict__ f_b2,
                    float* __restrict__ out)
{
    extern __shared__ float sh[];
    float* s1w   = sh + OFF_S1W;
    float* s2w   = sh + OFF_S2W;
    float* fw    = sh + OFF_FW;
    float* xall  = sh + OFF_XALL;
    float* featsI= sh + OFF_FEATS;
    float* smf   = sh + OFF_SMF;
    float* musS  = sh + OFF_MUS;
    float* c1s   = sh + OFF_C1;
    float* c2s   = sh + OFF_C2;
    float* cfs   = sh + OFF_CF;
    float* w2a   = sh + OFF_W2A;
    float* w2b   = sh + OFF_W2B;
    float* HfT   = sh + OFF_HFT;
    float* bacc  = sh + OFF_BACC;

    const int tid = threadIdx.x;
    const int b = blockIdx.x / NN;
    const int i = blockIdx.x % NN;
    const float* st = state + (size_t)b * ROWLEN;

    // ---- phase 1: cooperative loads ----
    for (int t = tid; t < NN*3; t += 256) xall[t] = st[t];
    if (tid < FF) featsI[tid] = st[NN*3 + i*FF + tid];
    if (tid < NRBF) musS[tid] = mus[tid];
    if (tid < HH) { w2a[tid] = s1_W2[tid]; w2b[tid] = s2_W2[tid]; HfT[tid] = 0.f; }
    if (tid < 8) bacc[tid] = 0.f;
    for (int t = tid; t < NRBF*HH; t += 256) {
        s1w[t] = s1_W1[t];
        s2w[t] = s2_W1[t];
        fw[t]  = f_W1[t];
    }
    __syncthreads();

    // ---- softmax of feats (warp 0) ----
    if (tid < 32) {
        float v = featsI[tid];
        float mx = v;
        #pragma unroll
        for (int o = 16; o; o >>= 1) mx = fmaxf(mx, __shfl_xor_sync(0xffffffffu, mx, o));
        float e = __expf(v - mx);
        float s = e;
        #pragma unroll
        for (int o = 16; o; o >>= 1) s += __shfl_xor_sync(0xffffffffu, s, o);
        smf[tid] = __fdividef(e, s);
    }
    __syncthreads();

    // ---- per-site constant hidden offsets c1/c2/cf ----
    if (tid < HH) {
        int h = tid;
        float a = s1_b1[h];
        #pragma unroll 8
        for (int f = 0; f < FF; f++)
            a += featsI[f] * (s1_W1[(NRBF+f)*HH + h] + s1_W1[(NRBF+FF+f)*HH + h]);
        c1s[h] = a;
        float af = f_b1[h];
        #pragma unroll 8
        for (int f = 0; f < FF; f++)
            af += smf[f] * f_W1[(NRBF+f)*HH + h];
        cfs[h] = af;
    } else {
        int h = tid - HH;
        float a = s2_b1[h];
        #pragma unroll 8
        for (int f = 0; f < FF; f++)
            a += featsI[f] * (s2_W1[(NRBF+f)*HH + h] + s2_W1[(NRBF+FF+f)*HH + h]);
        c2s[h] = a;
    }
    __syncthreads();

    // ---- pair loop: warp per pair ----
    const int warp = tid >> 5, lane = tid & 31;
    const float gam = gamma_p[0];
    const float s1b2 = s1_b2[0], s2b2 = s2_b2[0];
    const float xi0 = xall[i*3+0], xi1 = xall[i*3+1], xi2 = xall[i*3+2];
    const float mu0 = musS[lane];
    const float mu1 = (lane < NRBF-32) ? musS[lane+32] : 0.f;

    const float4* s1w4 = (const float4*)s1w;
    const float4* s2w4 = (const float4*)s2w;
    const float4* fw4  = (const float4*)fw;
    const float4 c1v = ((const float4*)c1s)[lane];
    const float4 c2v = ((const float4*)c2s)[lane];
    const float4 cfv = ((const float4*)cfs)[lane];
    const float4 w2av = ((const float4*)w2a)[lane];
    const float4 w2bv = ((const float4*)w2b)[lane];

    float Hf0=0.f, Hf1=0.f, Hf2=0.f, Hf3=0.f;
    float aS10=0.f, aS11=0.f, aS12=0.f;
    float aS20=0.f, aS21=0.f, aS22=0.f;
    float aG=0.f, aS=0.f;

    for (int k = warp; k < NP; k += 8) {
        const int j = k + (k >= i);
        const float r0 = xi0 - xall[j*3+0];
        const float r1 = xi1 - xall[j*3+1];
        const float r2 = xi2 - xall[j*3+2];
        const float d2 = r0*r0 + r1*r1 + r2*r2;
        const float d  = sqrtf(d2 + EPSV);
        const float r2d = __fdividef(d2, d);

        // rbf + d(rbf)/dd distributed over lanes
        float t0 = d - mu0;
        float rb0 = __expf(-gam * t0 * t0);
        float db0 = -2.f * gam * t0 * rb0;
        float rb1 = 0.f, db1 = 0.f;
        if (lane < NRBF-32) {
            float t1 = d - mu1;
            rb1 = __expf(-gam * t1 * t1);
            db1 = -2.f * gam * t1 * rb1;
        }

        float4 a1 = c1v, a2 = c2v, af = cfv;
        float4 da = make_float4(0.f,0.f,0.f,0.f);

        #pragma unroll 8
        for (int m = 0; m < 32; m++) {
            const float rb = __shfl_sync(0xffffffffu, rb0, m);
            const float db = __shfl_sync(0xffffffffu, db0, m);
            const float4 w1 = s1w4[m*32 + lane];
            a1.x += rb*w1.x; a1.y += rb*w1.y; a1.z += rb*w1.z; a1.w += rb*w1.w;
            da.x += db*w1.x; da.y += db*w1.y; da.z += db*w1.z; da.w += db*w1.w;
            const float4 w2 = s2w4[m*32 + lane];
            a2.x += rb*w2.x; a2.y += rb*w2.y; a2.z += rb*w2.z; a2.w += rb*w2.w;
            const float4 wf = fw4[m*32 + lane];
            af.x += rb*wf.x; af.y += rb*wf.y; af.z += rb*wf.z; af.w += rb*wf.w;
        }
        #pragma unroll 6
        for (int m = 32; m < NRBF; m++) {
            const float rb = __shfl_sync(0xffffffffu, rb1, m-32);
            const float db = __shfl_sync(0xffffffffu, db1, m-32);
            const float4 w1 = s1w4[m*32 + lane];
            a1.x += rb*w1.x; a1.y += rb*w1.y; a1.z += rb*w1.z; a1.w += rb*w1.w;
            da.x += db*w1.x; da.y += db*w1.y; da.z += db*w1.z; da.w += db*w1.w;
            const float4 w2 = s2w4[m*32 + lane];
            a2.x += rb*w2.x; a2.y += rb*w2.y; a2.z += rb*w2.z; a2.w += rb*w2.w;
            const float4 wf = fw4[m*32 + lane];
            af.x += rb*wf.x; af.y += rb*wf.y; af.z += rb*wf.z; af.w += rb*wf.w;
        }

        // tail: silu, W2 dots, silu' for derivative, Hf accumulation
        float p1 = 0.f, p2 = 0.f, pg = 0.f;
        #define TAIL(AX, DX, WA, WB, AFX, HFX)                          \
        {                                                               \
            float sg = __fdividef(1.f, 1.f + __expf(-(AX)));            \
            p1 += (WA) * (AX) * sg;                                     \
            pg += (WA) * sg * (1.f + (AX)*(1.f - sg)) * (DX);           \
            float sg2 = __fdividef(1.f, 1.f + __expf(-(a2.AFX)));       \
            p2 += (WB) * (a2.AFX) * sg2;                                \
            float sgf = __fdividef(1.f, 1.f + __expf(-(af.AFX)));       \
            HFX += (af.AFX) * sgf;                                      \
        }
        TAIL(a1.x, da.x, w2av.x, w2bv.x, x, Hf0)
        TAIL(a1.y, da.y, w2av.y, w2bv.y, y, Hf1)
        TAIL(a1.z, da.z, w2av.z, w2bv.z, z, Hf2)
        TAIL(a1.w, da.w, w2av.w, w2bv.w, w, Hf3)
        #undef TAIL

        #pragma unroll
        for (int o = 16; o; o >>= 1) {
            p1 += __shfl_xor_sync(0xffffffffu, p1, o);
            p2 += __shfl_xor_sync(0xffffffffu, p2, o);
            pg += __shfl_xor_sync(0xffffffffu, pg, o);
        }
        const float s1v = p1 + s1b2;
        const float s2v = p2 + s2b2;
        const float gd  = pg * r2d;

        aS10 += r0*s1v; aS11 += r1*s1v; aS12 += r2*s1v;
        aS20 += r0*s2v; aS21 += r1*s2v; aS22 += r2*s2v;
        aG += gd; aS += s1v;
    }

    // ---- block reductions ----
    if (lane == 0) {
        atomicAdd(&bacc[0], aS10); atomicAdd(&bacc[1], aS11); atomicAdd(&bacc[2], aS12);
        atomicAdd(&bacc[3], aS20); atomicAdd(&bacc[4], aS21); atomicAdd(&bacc[5], aS22);
        atomicAdd(&bacc[6], aG);   atomicAdd(&bacc[7], aS);
    }
    atomicAdd(&HfT[4*lane+0], Hf0);
    atomicAdd(&HfT[4*lane+1], Hf1);
    atomicAdd(&HfT[4*lane+2], Hf2);
    atomicAdd(&HfT[4*lane+3], Hf3);
    __syncthreads();

    // ---- epilogue ----
    if (tid == 0) {
        const float inv = 1.f / (float)NP;
        float vx0 = bacc[0]*inv, vx1 = bacc[1]*inv, vx2 = bacc[2]*inv;
        float cc0 = bacc[3]*inv, cc1 = bacc[4]*inv, cc2 = bacc[5]*inv;
        // v_x + cross(mean(r*s2), v_x)
        float o0 = vx0 + (cc1*vx2 - cc2*vx1);
        float o1 = vx1 + (cc2*vx0 - cc0*vx2);
        float o2 = vx2 + (cc0*vx1 - cc1*vx0);
        g_vx[(b*NN+i)*3+0] = o0;
        g_vx[(b*NN+i)*3+1] = o1;
        g_vx[(b*NN+i)*3+2] = o2;
        g_tp[b*NN+i] = bacc[6] + (float)DD * bacc[7];
    }
    if (tid < FF) {
        float a = 0.f;
        #pragma unroll 16
        for (int h = 0; h < HH; h++) a += HfT[h] * f_W2[h*FF + tid];
        out[(size_t)b*ROWLEN + NN*DD + i*FF + tid] = a / (float)NP + f_b2[tid];
    }
}

__global__ void fd_finalize_kernel(float* __restrict__ out)
{
    const int b = blockIdx.x;
    const int i = threadIdx.x;  // 256 threads = N atoms
    __shared__ float sd[NN];

    float v0 = g_vx[(b*NN+i)*3+0];
    float v1 = g_vx[(b*NN+i)*3+1];
    float v2 = g_vx[(b*NN+i)*3+2];
    float tp = g_tp[b*NN+i];

    float sums[4];
    float vals[4] = {v0, v1, v2, tp};
    #pragma unroll
    for (int q = 0; q < 4; q++) {
        sd[i] = vals[q];
        __syncthreads();
        for (int s = NN/2; s > 0; s >>= 1) {
            if (i < s) sd[i] += sd[i+s];
            __syncthreads();
        }
        sums[q] = sd[0];
        __syncthreads();
    }
    const float m0 = sums[0] / (float)NN;
    const float m1 = sums[1] / (float)NN;
    const float m2 = sums[2] / (float)NN;

    out[(size_t)b*ROWLEN + i*3+0] = v0 - m0;
    out[(size_t)b*ROWLEN + i*3+1] = v1 - m1;
    out[(size_t)b*ROWLEN + i*3+2] = v2 - m2;
    if (i == 0)
        out[(size_t)BB*ROWLEN + b] = sums[3] / (float)NP;
}

extern "C" void kernel_launch(void* const* d_in, const int* in_sizes, int n_in,
                              void* d_out, int out_size)
{
    const float* state = (const float*)d_in[1];
    const float* mus   = (const float*)d_in[2];
    const float* gamma = (const float*)d_in[3];
    const float* s1_W1 = (const float*)d_in[4];
    const float* s1_b1 = (const float*)d_in[5];
    const float* s1_W2 = (const float*)d_in[6];
    const float* s1_b2 = (const float*)d_in[7];
    const float* s2_W1 = (const float*)d_in[8];
    const float* s2_b1 = (const float*)d_in[9];
    const float* s2_W2 = (const float*)d_in[10];
    const float* s2_b2 = (const float*)d_in[11];
    const float* f_W1  = (const float*)d_in[12];
    const float* f_b1  = (const float*)d_in[13];
    const float* f_W2  = (const float*)d_in[14];
    const float* f_b2  = (const float*)d_in[15];
    float* out = (float*)d_out;

    cudaFuncSetAttribute(fd_site_kernel,
                         cudaFuncAttributeMaxDynamicSharedMemorySize, SMEM_BYTES);

    fd_site_kernel<<<BB*NN, 256, SMEM_BYTES>>>(
        state, mus, gamma,
        s1_W1, s1_b1, s1_W2, s1_b2,
        s2_W1, s2_b1, s2_W2, s2_b2,
        f_W1, f_b1, f_W2, f_b2, out);

    fd_finalize_kernel<<<BB, NN>>>(out);
}